// round 11
// baseline (speedup 1.0000x reference)
#include <cuda_runtime.h>
#include <math.h>
#include <stdint.h>

#define NN    30000
#define LSEQ  5
#define KFAN  16
#define NG    512   // 2 dirs * 4 gates * 64 hidden
#define NB    8     // nodes per recurrence block

// ---------------- scratch (device globals: sanctioned allocation path) ----
__device__ float g_xg[NN * LSEQ * NG];
__device__ float g_P0[NN * NG];
__device__ float g_P1[NN * NG];
__device__ float g_c0[NN * 128];
__device__ float g_c1[NN * 128];
__device__ float g_n0[NN * 128];
__device__ float g_n1[NN * 128];
__device__ float g_n2[NN * 128];
__device__ float g_n3[NN * 128];

// ---------------- fast transcendentals ------------------------------------
__device__ __forceinline__ float ftanh(float x) {
    float y;
    asm("tanh.approx.f32 %0, %1;" : "=f"(y) : "f"(x));
    return y;
}
__device__ __forceinline__ float fsigmoid(float x) {
    return fmaf(ftanh(0.5f * x), 0.5f, 0.5f);
}

// ---------------- GEMM (SIMT, packed f32x2 FMA) ----------------------------
// C[m, j] = bias[j] + sum_d A[m,d] * W[j,d]
// A: [M,128] f32 row-major.  W: [512,128] f32 row-major.
// 128x128 tile, K=128 single smem stage (135KB, 1 block/SM), 256 threads,
// 8x8 per-thread tile. Inner loop uses fma.rn.f32x2 (FFMA2): n-columns
// packed in pairs -> 32 FFMA2/d instead of 64 FFMA/d, doubling the fp32
// math rate (the measured bound of the R4 SIMT version).
__global__ __launch_bounds__(256, 1) void gemm_gates(
    const float* __restrict__ A, int M,
    const float* __restrict__ W,
    const float* __restrict__ bias,
    float* __restrict__ C)
{
    extern __shared__ float sm[];
    float* As = sm;              // [128 m][132] (padded)
    float* Bs = sm + 128 * 132;  // [128 d][132 n] (transposed, padded)
    const int tid = threadIdx.x;
    const int j0 = blockIdx.x * 128;   // N slice (0..3) fastest -> A slab L2-hot
    const int m0 = blockIdx.y * 128;

    // stage A (coalesced along d, row-major in smem)
    {
        int row = tid >> 5;   // 0..7
        int dc  = tid & 31;   // float4 chunk along d
        #pragma unroll
        for (int p = 0; p < 16; ++p) {
            int r = row + p * 8;
            int gm = m0 + r;
            float4 v = make_float4(0.f, 0.f, 0.f, 0.f);
            if (gm < M) v = reinterpret_cast<const float4*>(A)[(size_t)gm * 32 + dc];
            *reinterpret_cast<float4*>(&As[r * 132 + dc * 4]) = v;
        }
    }
    // stage B transposed (d-major in smem). W slice is tiny & L2-hot.
    {
        int col  = tid & 127;
        int half = tid >> 7;
        const float4* Wr = reinterpret_cast<const float4*>(
            W + (size_t)(j0 + col) * 128 + half * 64);
        #pragma unroll
        for (int dc = 0; dc < 16; ++dc) {
            float4 v = Wr[dc];
            int d = half * 64 + dc * 4;
            Bs[(d + 0) * 132 + col] = v.x;
            Bs[(d + 1) * 132 + col] = v.y;
            Bs[(d + 2) * 132 + col] = v.z;
            Bs[(d + 3) * 132 + col] = v.w;
        }
    }
    __syncthreads();

    const int tx = tid & 15;   // n-group (8 cols = 4 f32x2 pairs)
    const int ty = tid >> 4;   // m-group (8 rows)

    // accumulators as packed f32x2 (n-pairs)
    unsigned long long acc[8][4];
    #pragma unroll
    for (int r = 0; r < 8; ++r)
        #pragma unroll
        for (int c2 = 0; c2 < 4; ++c2) acc[r][c2] = 0ull;

    const float* Arow = &As[ty * 8 * 132];
    #pragma unroll 4
    for (int d = 0; d < 128; d += 2) {
        // a: 8 rows x 2 d  (LDS.64, half-warp uniform -> cheap wavefronts)
        float2 a2[8];
        #pragma unroll
        for (int r = 0; r < 8; ++r)
            a2[r] = *reinterpret_cast<const float2*>(&Arow[r * 132 + d]);

        #pragma unroll
        for (int s = 0; s < 2; ++s) {
            // b pairs for this d: 4 x f32x2 via two 16B loads
            const float* brow = &Bs[(d + s) * 132 + tx * 8];
            ulonglong2 q0 = *reinterpret_cast<const ulonglong2*>(brow);
            ulonglong2 q1 = *reinterpret_cast<const ulonglong2*>(brow + 4);
            unsigned long long bb[4] = {q0.x, q0.y, q1.x, q1.y};

            #pragma unroll
            for (int r = 0; r < 8; ++r) {
                float av = s ? a2[r].y : a2[r].x;
                unsigned long long ad;
                asm("mov.b64 %0, {%1,%1};" : "=l"(ad) : "f"(av));
                #pragma unroll
                for (int c2 = 0; c2 < 4; ++c2)
                    asm("fma.rn.f32x2 %0, %1, %2, %0;"
                        : "+l"(acc[r][c2]) : "l"(ad), "l"(bb[c2]));
            }
        }
    }

    float bv[8];
    #pragma unroll
    for (int c = 0; c < 8; ++c) bv[c] = bias[j0 + tx * 8 + c];
    #pragma unroll
    for (int r = 0; r < 8; ++r) {
        int gm = m0 + ty * 8 + r;
        if (gm < M) {
            float o[8];
            #pragma unroll
            for (int c2 = 0; c2 < 4; ++c2) {
                float lo, hi;
                asm("mov.b64 {%0,%1}, %2;" : "=f"(lo), "=f"(hi) : "l"(acc[r][c2]));
                o[c2 * 2 + 0] = lo + bv[c2 * 2 + 0];
                o[c2 * 2 + 1] = hi + bv[c2 * 2 + 1];
            }
            float4* Cp = reinterpret_cast<float4*>(C + (size_t)gm * NG + j0 + tx * 8);
            Cp[0] = make_float4(o[0], o[1], o[2], o[3]);
            Cp[1] = make_float4(o[4], o[5], o[6], o[7]);
        }
    }
}

// ---------------- bi-LSTM recurrence + mean (measured-good v2) -------------
__global__ __launch_bounds__(512, 1) void recur_kernel(
    const float* __restrict__ xg,
    const int* __restrict__ idx,
    int T,
    const float* __restrict__ Whh,
    float* __restrict__ out)
{
    __shared__ float h_s[NB][128];
    __shared__ float g_s[NB][NG];
    __shared__ int   sIdx[NB * 17];
    const int tid = threadIdx.x;
    const int dir = tid >> 8;
    const int node0 = blockIdx.x * NB;

    if (tid < NB * T) {
        int i = tid / T, t = tid % T;
        int seq = (node0 + i) * T + t;
        sIdx[i * 17 + t] = idx ? idx[seq] : seq;
    }

    float whh[64];
    {
        const float4* wp = reinterpret_cast<const float4*>(Whh + (size_t)tid * 64);
        #pragma unroll
        for (int e4 = 0; e4 < 16; ++e4) {
            float4 v = wp[e4];
            whh[e4 * 4 + 0] = v.x; whh[e4 * 4 + 1] = v.y;
            whh[e4 * 4 + 2] = v.z; whh[e4 * 4 + 3] = v.w;
        }
    }

    float cst[2]  = {0.f, 0.f};
    float hsum[2] = {0.f, 0.f};
    #pragma unroll
    for (int q = 0; q < 2; ++q) {
        int u = tid + q * 512;
        h_s[u >> 7][u & 127] = 0.f;
    }
    __syncthreads();

    float cur[NB], nxt[NB];
    #pragma unroll
    for (int i = 0; i < NB; ++i) nxt[i] = 0.f;
    {
        const int trow = dir ? (T - 1) : 0;
        #pragma unroll
        for (int i = 0; i < NB; ++i)
            cur[i] = xg[(size_t)sIdx[i * 17 + trow] * NG + tid];
    }

    for (int t = 0; t < T; ++t) {
        if (t + 1 < T) {
            const int trow = dir ? (T - 2 - t) : (t + 1);
            #pragma unroll
            for (int i = 0; i < NB; ++i)
                nxt[i] = xg[(size_t)sIdx[i * 17 + trow] * NG + tid];
        }

        #pragma unroll
        for (int i = 0; i < NB; ++i) {
            const float4* h4 = reinterpret_cast<const float4*>(&h_s[i][dir * 64]);
            float a0 = cur[i], a1 = 0.f;
            #pragma unroll
            for (int e4 = 0; e4 < 16; e4 += 2) {
                float4 ha = h4[e4];
                float4 hb = h4[e4 + 1];
                a0 += whh[e4 * 4 + 0] * ha.x;
                a0 += whh[e4 * 4 + 1] * ha.y;
                a0 += whh[e4 * 4 + 2] * ha.z;
                a0 += whh[e4 * 4 + 3] * ha.w;
                a1 += whh[e4 * 4 + 4] * hb.x;
                a1 += whh[e4 * 4 + 5] * hb.y;
                a1 += whh[e4 * 4 + 6] * hb.z;
                a1 += whh[e4 * 4 + 7] * hb.w;
            }
            g_s[i][tid] = a0 + a1;
        }
        __syncthreads();

        #pragma unroll
        for (int q = 0; q < 2; ++q) {
            int u = tid + q * 512;
            int i = u >> 7, r = u & 127;
            int dd = r >> 6, e = r & 63;
            const float* gg = &g_s[i][dd * 256];
            float si = fsigmoid(gg[e]);
            float sf = fsigmoid(gg[64 + e]);
            float so = fsigmoid(gg[192 + e]);
            float gt = ftanh(gg[128 + e]);
            float c = sf * cst[q] + si * gt;
            float h = so * ftanh(c);
            cst[q] = c;
            h_s[i][r] = h;
            hsum[q] += h;
        }
        __syncthreads();

        #pragma unroll
        for (int i = 0; i < NB; ++i) cur[i] = nxt[i];
    }

    const float invT = 1.f / (float)T;
    #pragma unroll
    for (int q = 0; q < 2; ++q) {
        int u = tid + q * 512;
        int i = u >> 7, r = u & 127;
        out[(size_t)(node0 + i) * 128 + r] = hsum[q] * invT;
    }
}

// ---------------- attention combine ---------------------------------------
__global__ void combine_kernel(
    const float* __restrict__ cA, const float* __restrict__ cB,
    const float* __restrict__ nAA, const float* __restrict__ nBA,
    const float* __restrict__ nAB, const float* __restrict__ nBB,
    const float* __restrict__ attnA, const float* __restrict__ attnB,
    float* __restrict__ out)
{
    int gw   = (blockIdx.x * blockDim.x + threadIdx.x) >> 5;
    int lane = threadIdx.x & 31;
    if (gw >= 2 * NN) return;
    int tp = gw >= NN;
    int node = gw - tp * NN;

    const float* c  = (tp ? cB  : cA)  + (size_t)node * 128;
    const float* n1 = (tp ? nAB : nAA) + (size_t)node * 128;
    const float* n2 = (tp ? nBB : nBA) + (size_t)node * 128;
    const float* at = tp ? attnB : attnA;

    float4 c4  = reinterpret_cast<const float4*>(c)[lane];
    float4 n14 = reinterpret_cast<const float4*>(n1)[lane];
    float4 n24 = reinterpret_cast<const float4*>(n2)[lane];
    float4 a1  = reinterpret_cast<const float4*>(at)[lane];
    float4 a2  = reinterpret_cast<const float4*>(at + 128)[lane];

    float d0 = a1.x * c4.x + a1.y * c4.y + a1.z * c4.z + a1.w * c4.w;
    float dc = a2.x * c4.x + a2.y * c4.y + a2.z * c4.z + a2.w * c4.w;
    float d1 = a2.x * n14.x + a2.y * n14.y + a2.z * n14.z + a2.w * n14.w;
    float d2 = a2.x * n24.x + a2.y * n24.y + a2.z * n24.z + a2.w * n24.w;
    #pragma unroll
    for (int o = 16; o > 0; o >>= 1) {
        d0 += __shfl_xor_sync(0xffffffffu, d0, o);
        dc += __shfl_xor_sync(0xffffffffu, dc, o);
        d1 += __shfl_xor_sync(0xffffffffu, d1, o);
        d2 += __shfl_xor_sync(0xffffffffu, d2, o);
    }
    float s0 = d0 + dc; s0 = s0 > 0.f ? s0 : 0.01f * s0;
    float s1 = d0 + d1; s1 = s1 > 0.f ? s1 : 0.01f * s1;
    float s2 = d0 + d2; s2 = s2 > 0.f ? s2 : 0.01f * s2;
    float mx = fmaxf(s0, fmaxf(s1, s2));
    float e0 = expf(s0 - mx), e1 = expf(s1 - mx), e2 = expf(s2 - mx);
    float inv = 1.f / (e0 + e1 + e2);
    e0 *= inv; e1 *= inv; e2 *= inv;

    float4 o4;
    o4.x = e0 * c4.x + e1 * n14.x + e2 * n24.x;
    o4.y = e0 * c4.y + e1 * n14.y + e2 * n24.y;
    o4.z = e0 * c4.z + e1 * n14.z + e2 * n24.z;
    o4.w = e0 * c4.w + e1 * n14.w + e2 * n24.w;
    reinterpret_cast<float4*>(out + (size_t)tp * NN * 128 + (size_t)node * 128)[lane] = o4;
}

// ---------------- launch ---------------------------------------------------
extern "C" void kernel_launch(void* const* d_in, const int* in_sizes, int n_in,
                              void* d_out, int out_size)
{
    const float* feats_a = (const float*)d_in[0];
    const float* feats_b = (const float*)d_in[1];
    const float* Wih_ca = (const float*)d_in[2];
    const float* Whh_ca = (const float*)d_in[3];
    const float* b_ca   = (const float*)d_in[4];
    const float* Wih_cb = (const float*)d_in[5];
    const float* Whh_cb = (const float*)d_in[6];
    const float* b_cb   = (const float*)d_in[7];
    const float* Wih_na = (const float*)d_in[8];
    const float* Whh_na = (const float*)d_in[9];
    const float* b_na   = (const float*)d_in[10];
    const float* Wih_nb = (const float*)d_in[11];
    const float* Whh_nb = (const float*)d_in[12];
    const float* b_nb   = (const float*)d_in[13];
    const float* attn_a = (const float*)d_in[14];
    const float* attn_b = (const float*)d_in[15];
    const int* idx_a_a = (const int*)d_in[16];
    const int* idx_b_a = (const int*)d_in[17];
    const int* idx_a_b = (const int*)d_in[18];
    const int* idx_b_b = (const int*)d_in[19];
    float* out = (float*)d_out;
    (void)in_sizes; (void)n_in; (void)out_size;

    float *xg, *P0, *P1, *c0, *c1, *n0, *n1, *n2, *n3;
    cudaGetSymbolAddress((void**)&xg, g_xg);
    cudaGetSymbolAddress((void**)&P0, g_P0);
    cudaGetSymbolAddress((void**)&P1, g_P1);
    cudaGetSymbolAddress((void**)&c0, g_c0);
    cudaGetSymbolAddress((void**)&c1, g_c1);
    cudaGetSymbolAddress((void**)&n0, g_n0);
    cudaGetSymbolAddress((void**)&n1, g_n1);
    cudaGetSymbolAddress((void**)&n2, g_n2);
    cudaGetSymbolAddress((void**)&n3, g_n3);

    const size_t GSM = 2u * 128u * 132u * sizeof(float);  // 135168B
    cudaFuncSetAttribute(gemm_gates, cudaFuncAttributeMaxDynamicSharedMemorySize, (int)GSM);

    dim3 ggC(4, (NN * LSEQ + 127) / 128);   // N-slices fastest: A slab L2-hot
    dim3 ggP(4, (NN + 127) / 128);
    const int RB = NN / NB;  // 3750

    // content bi-LSTMs
    gemm_gates<<<ggC, 256, GSM>>>(feats_a, NN * LSEQ, Wih_ca, b_ca, xg);
    recur_kernel<<<RB, 512>>>(xg, nullptr, LSEQ, Whh_ca, c0);
    gemm_gates<<<ggC, 256, GSM>>>(feats_b, NN * LSEQ, Wih_cb, b_cb, xg);
    recur_kernel<<<RB, 512>>>(xg, nullptr, LSEQ, Whh_cb, c1);

    // per-src-node neighbor input gates (amortizes the gather GEMM 16x)
    gemm_gates<<<ggP, 256, GSM>>>(c0, NN, Wih_na, b_na, P0);
    gemm_gates<<<ggP, 256, GSM>>>(c1, NN, Wih_nb, b_nb, P1);

    // neighbor bi-LSTMs; P0 consumers adjacent, then P1 (L2 reuse)
    recur_kernel<<<RB, 512>>>(P0, idx_a_a, KFAN, Whh_na, n0);
    recur_kernel<<<RB, 512>>>(P0, idx_a_b, KFAN, Whh_na, n2);
    recur_kernel<<<RB, 512>>>(P1, idx_b_a, KFAN, Whh_nb, n1);
    recur_kernel<<<RB, 512>>>(P1, idx_b_b, KFAN, Whh_nb, n3);

    // attention combine
    combine_kernel<<<(2 * NN * 32 + 255) / 256, 256>>>(
        c0, c1, n0, n1, n2, n3, attn_a, attn_b, out);
}

// round 12
// speedup vs baseline: 1.0872x; 1.0872x over previous
#include <cuda_runtime.h>
#include <math.h>
#include <stdint.h>

#define NN    30000
#define LSEQ  5
#define KFAN  16
#define NG    512   // 2 dirs * 4 gates * 64 hidden
#define NB    8     // nodes per recurrence block

// ---------------- scratch (device globals: sanctioned allocation path) ----
__device__ float g_xg[NN * LSEQ * NG];
__device__ float g_P0[NN * NG];
__device__ float g_P1[NN * NG];
__device__ float g_c0[NN * 128];
__device__ float g_c1[NN * 128];
__device__ float g_n0[NN * 128];
__device__ float g_n1[NN * 128];
__device__ float g_n2[NN * 128];
__device__ float g_n3[NN * 128];

// ---------------- fast transcendentals ------------------------------------
__device__ __forceinline__ float ftanh(float x) {
    float y;
    asm("tanh.approx.f32 %0, %1;" : "=f"(y) : "f"(x));
    return y;
}
__device__ __forceinline__ float fsigmoid(float x) {
    return fmaf(ftanh(0.5f * x), 0.5f, 0.5f);
}
__device__ __forceinline__ uint32_t f2tf32(float x) {
    uint32_t u;
    asm("cvt.rna.tf32.f32 %0, %1;" : "=r"(u) : "f"(x));
    return u;
}

// ---------------- GEMM (tf32 mma, R8 measured-best, verbatim) --------------
// C[m, j] = bias[j] + sum_d A[m,d] * W[j,d]
// Block tile 128(M) x 128(N), K=128 staged in smem as tf32. 256 threads,
// 8 warps in 4(M) x 2(N); warp = 32x64 via 2x8 m16n8k8 atoms.
__global__ __launch_bounds__(256, 1) void gemm_gates(
    const float* __restrict__ A, int M,
    const float* __restrict__ W,
    const float* __restrict__ bias,
    float* __restrict__ C)
{
    extern __shared__ float sm[];
    uint32_t* Au = reinterpret_cast<uint32_t*>(sm);              // [128 m][132]
    uint32_t* Bu = reinterpret_cast<uint32_t*>(sm) + 128 * 132;  // [128 n][132]
    __shared__ float sBias[128];
    const int tid = threadIdx.x;
    const int j0 = blockIdx.x * 128;   // N slice (0..3)
    const int m0 = blockIdx.y * 128;

    if (tid < 128) sBias[tid] = bias[j0 + tid];

    #pragma unroll
    for (int p = 0; p < 16; ++p) {
        int idx = tid + p * 256;
        int row = idx >> 5;
        int c4  = idx & 31;
        int gm = m0 + row;
        float4 v = make_float4(0.f, 0.f, 0.f, 0.f);
        if (gm < M) v = reinterpret_cast<const float4*>(A)[(size_t)gm * 32 + c4];
        uint4 u = make_uint4(f2tf32(v.x), f2tf32(v.y), f2tf32(v.z), f2tf32(v.w));
        *reinterpret_cast<uint4*>(&Au[row * 132 + c4 * 4]) = u;
    }
    #pragma unroll
    for (int p = 0; p < 16; ++p) {
        int idx = tid + p * 256;
        int row = idx >> 5;
        int c4  = idx & 31;
        float4 v = reinterpret_cast<const float4*>(W)[(size_t)(j0 + row) * 32 + c4];
        uint4 u = make_uint4(f2tf32(v.x), f2tf32(v.y), f2tf32(v.z), f2tf32(v.w));
        *reinterpret_cast<uint4*>(&Bu[row * 132 + c4 * 4]) = u;
    }
    __syncthreads();

    const int lane = tid & 31;
    const int warp = tid >> 5;
    const int wm = warp & 3;
    const int wn = warp >> 2;
    const int g  = lane >> 2;
    const int tg = lane & 3;

    float acc[2][8][4];
    #pragma unroll
    for (int ma = 0; ma < 2; ++ma)
        #pragma unroll
        for (int na = 0; na < 8; ++na)
            #pragma unroll
            for (int e = 0; e < 4; ++e) acc[ma][na][e] = 0.f;

    #pragma unroll 4
    for (int ks = 0; ks < 16; ++ks) {
        const int k0 = ks * 8;
        uint32_t af[2][4];
        #pragma unroll
        for (int ma = 0; ma < 2; ++ma) {
            const uint32_t* ap = Au + (wm * 32 + ma * 16 + g) * 132 + k0 + tg;
            af[ma][0] = ap[0];
            af[ma][2] = ap[4];
            af[ma][1] = ap[8 * 132];
            af[ma][3] = ap[8 * 132 + 4];
        }
        uint32_t bf[8][2];
        #pragma unroll
        for (int na = 0; na < 8; ++na) {
            const uint32_t* bp = Bu + (wn * 64 + na * 8 + g) * 132 + k0 + tg;
            bf[na][0] = bp[0];
            bf[na][1] = bp[4];
        }
        #pragma unroll
        for (int ma = 0; ma < 2; ++ma)
            #pragma unroll
            for (int na = 0; na < 8; ++na)
                asm volatile(
                    "mma.sync.aligned.m16n8k8.row.col.f32.tf32.tf32.f32 "
                    "{%0,%1,%2,%3}, {%4,%5,%6,%7}, {%8,%9}, {%0,%1,%2,%3};"
                    : "+f"(acc[ma][na][0]), "+f"(acc[ma][na][1]),
                      "+f"(acc[ma][na][2]), "+f"(acc[ma][na][3])
                    : "r"(af[ma][0]), "r"(af[ma][1]), "r"(af[ma][2]), "r"(af[ma][3]),
                      "r"(bf[na][0]), "r"(bf[na][1]));
    }

    #pragma unroll
    for (int ma = 0; ma < 2; ++ma) {
        #pragma unroll
        for (int half = 0; half < 2; ++half) {
            int gm = m0 + wm * 32 + ma * 16 + g + half * 8;
            if (gm < M) {
                float* Crow = C + (size_t)gm * NG + j0;
                #pragma unroll
                for (int na = 0; na < 8; ++na) {
                    int n = wn * 64 + na * 8 + tg * 2;
                    float2 o;
                    o.x = acc[ma][na][half * 2 + 0] + sBias[n];
                    o.y = acc[ma][na][half * 2 + 1] + sBias[n + 1];
                    *reinterpret_cast<float2*>(Crow + n) = o;
                }
            }
        }
    }
}

// ---------------- bi-LSTM recurrence + mean (v5: split-half gate pairing) --
// Thread owns TWO gates (j0 = dir*256 + jj, j1 = j0 + 128) but only HALF the
// h vector (32 of 64 elements); halves combined with one shfl.xor(1) per
// gate. Halves the dominant h-broadcast LDS instruction count (the measured
// 31K cyc/block bound) at unchanged FMA totals and <=128 regs.
__global__ __launch_bounds__(512, 1) void recur_kernel(
    const float* __restrict__ xg,
    const int* __restrict__ idx,
    int T,
    const float* __restrict__ Whh,   // [512 * 64] row-major
    float* __restrict__ out)         // [NN * 128]
{
    __shared__ float h_s[NB][128];
    __shared__ float g_s[NB][NG];
    __shared__ int   sIdx[NB * 17];
    const int tid  = threadIdx.x;
    const int dir  = tid >> 8;            // warp-uniform
    const int half = tid & 1;
    const int jj   = (tid & 255) >> 1;    // 0..127
    const int j0g  = dir * 256 + jj;      // gate A
    const int j1g  = j0g + 128;           // gate B
    const int jme  = half ? j1g : j0g;    // gate whose xg/g_s this thread owns
    const int node0 = blockIdx.x * NB;

    if (tid < NB * T) {
        int i = tid / T, t = tid % T;
        int seq = (node0 + i) * T + t;
        sIdx[i * 17 + t] = idx ? idx[seq] : seq;
    }

    // whh: half-rows of both gates (32 + 32 regs)
    float whh0[32], whh1[32];
    {
        const float4* wp0 = reinterpret_cast<const float4*>(
            Whh + (size_t)j0g * 64 + half * 32);
        const float4* wp1 = reinterpret_cast<const float4*>(
            Whh + (size_t)j1g * 64 + half * 32);
        #pragma unroll
        for (int e4 = 0; e4 < 8; ++e4) {
            float4 v0 = wp0[e4];
            whh0[e4 * 4 + 0] = v0.x; whh0[e4 * 4 + 1] = v0.y;
            whh0[e4 * 4 + 2] = v0.z; whh0[e4 * 4 + 3] = v0.w;
            float4 v1 = wp1[e4];
            whh1[e4 * 4 + 0] = v1.x; whh1[e4 * 4 + 1] = v1.y;
            whh1[e4 * 4 + 2] = v1.z; whh1[e4 * 4 + 3] = v1.w;
        }
    }

    float cst[2]  = {0.f, 0.f};
    float hsum[2] = {0.f, 0.f};
    #pragma unroll
    for (int q = 0; q < 2; ++q) {
        int u = tid + q * 512;
        h_s[u >> 7][u & 127] = 0.f;
    }
    __syncthreads();

    // prefetch t=0 gather rows (one xg float per node: this thread's gate)
    float cur[NB], nxt[NB];
    #pragma unroll
    for (int i = 0; i < NB; ++i) nxt[i] = 0.f;
    {
        const int trow = dir ? (T - 1) : 0;
        #pragma unroll
        for (int i = 0; i < NB; ++i)
            cur[i] = xg[(size_t)sIdx[i * 17 + trow] * NG + jme];
    }

    for (int t = 0; t < T; ++t) {
        if (t + 1 < T) {
            const int trow = dir ? (T - 2 - t) : (t + 1);
            #pragma unroll
            for (int i = 0; i < NB; ++i)
                nxt[i] = xg[(size_t)sIdx[i * 17 + trow] * NG + jme];
        }

        #pragma unroll
        for (int i = 0; i < NB; ++i) {
            const float4* h4 = reinterpret_cast<const float4*>(
                &h_s[i][dir * 64 + half * 32]);   // this half's 32 h floats
            // partials: accA for gate j0g, accB for gate j1g; the xg value of
            // this thread's gate is folded into its own partial pre-shuffle.
            float accA = half ? 0.f : cur[i];
            float accB = half ? cur[i] : 0.f;
            #pragma unroll
            for (int e4 = 0; e4 < 8; ++e4) {
                float4 h = h4[e4];
                accA += whh0[e4 * 4 + 0] * h.x;
                accB += whh1[e4 * 4 + 0] * h.x;
                accA += whh0[e4 * 4 + 1] * h.y;
                accB += whh1[e4 * 4 + 1] * h.y;
                accA += whh0[e4 * 4 + 2] * h.z;
                accB += whh1[e4 * 4 + 2] * h.z;
                accA += whh0[e4 * 4 + 3] * h.w;
                accB += whh1[e4 * 4 + 3] * h.w;
            }
            accA += __shfl_xor_sync(0xffffffffu, accA, 1);
            accB += __shfl_xor_sync(0xffffffffu, accB, 1);
            g_s[i][jme] = half ? accB : accA;
        }
        __syncthreads();

        #pragma unroll
        for (int q = 0; q < 2; ++q) {
            int u = tid + q * 512;
            int i = u >> 7, r = u & 127;
            int dd = r >> 6, e = r & 63;
            const float* gg = &g_s[i][dd * 256];
            float si = fsigmoid(gg[e]);
            float sf = fsigmoid(gg[64 + e]);
            float so = fsigmoid(gg[192 + e]);
            float gt = ftanh(gg[128 + e]);
            float c = sf * cst[q] + si * gt;
            float h = so * ftanh(c);
            cst[q] = c;
            h_s[i][r] = h;
            hsum[q] += h;
        }
        __syncthreads();

        #pragma unroll
        for (int i = 0; i < NB; ++i) cur[i] = nxt[i];
    }

    const float invT = 1.f / (float)T;
    #pragma unroll
    for (int q = 0; q < 2; ++q) {
        int u = tid + q * 512;
        int i = u >> 7, r = u & 127;
        out[(size_t)(node0 + i) * 128 + r] = hsum[q] * invT;
    }
}

// ---------------- attention combine ---------------------------------------
__global__ void combine_kernel(
    const float* __restrict__ cA, const float* __restrict__ cB,
    const float* __restrict__ nAA, const float* __restrict__ nBA,
    const float* __restrict__ nAB, const float* __restrict__ nBB,
    const float* __restrict__ attnA, const float* __restrict__ attnB,
    float* __restrict__ out)
{
    int gw   = (blockIdx.x * blockDim.x + threadIdx.x) >> 5;
    int lane = threadIdx.x & 31;
    if (gw >= 2 * NN) return;
    int tp = gw >= NN;
    int node = gw - tp * NN;

    const float* c  = (tp ? cB  : cA)  + (size_t)node * 128;
    const float* n1 = (tp ? nAB : nAA) + (size_t)node * 128;
    const float* n2 = (tp ? nBB : nBA) + (size_t)node * 128;
    const float* at = tp ? attnB : attnA;

    float4 c4  = reinterpret_cast<const float4*>(c)[lane];
    float4 n14 = reinterpret_cast<const float4*>(n1)[lane];
    float4 n24 = reinterpret_cast<const float4*>(n2)[lane];
    float4 a1  = reinterpret_cast<const float4*>(at)[lane];
    float4 a2  = reinterpret_cast<const float4*>(at + 128)[lane];

    float d0 = a1.x * c4.x + a1.y * c4.y + a1.z * c4.z + a1.w * c4.w;
    float dc = a2.x * c4.x + a2.y * c4.y + a2.z * c4.z + a2.w * c4.w;
    float d1 = a2.x * n14.x + a2.y * n14.y + a2.z * n14.z + a2.w * n14.w;
    float d2 = a2.x * n24.x + a2.y * n24.y + a2.z * n24.z + a2.w * n24.w;
    #pragma unroll
    for (int o = 16; o > 0; o >>= 1) {
        d0 += __shfl_xor_sync(0xffffffffu, d0, o);
        dc += __shfl_xor_sync(0xffffffffu, dc, o);
        d1 += __shfl_xor_sync(0xffffffffu, d1, o);
        d2 += __shfl_xor_sync(0xffffffffu, d2, o);
    }
    float s0 = d0 + dc; s0 = s0 > 0.f ? s0 : 0.01f * s0;
    float s1 = d0 + d1; s1 = s1 > 0.f ? s1 : 0.01f * s1;
    float s2 = d0 + d2; s2 = s2 > 0.f ? s2 : 0.01f * s2;
    float mx = fmaxf(s0, fmaxf(s1, s2));
    float e0 = expf(s0 - mx), e1 = expf(s1 - mx), e2 = expf(s2 - mx);
    float inv = 1.f / (e0 + e1 + e2);
    e0 *= inv; e1 *= inv; e2 *= inv;

    float4 o4;
    o4.x = e0 * c4.x + e1 * n14.x + e2 * n24.x;
    o4.y = e0 * c4.y + e1 * n14.y + e2 * n24.y;
    o4.z = e0 * c4.z + e1 * n14.z + e2 * n24.z;
    o4.w = e0 * c4.w + e1 * n14.w + e2 * n24.w;
    reinterpret_cast<float4*>(out + (size_t)tp * NN * 128 + (size_t)node * 128)[lane] = o4;
}

// ---------------- launch ---------------------------------------------------
extern "C" void kernel_launch(void* const* d_in, const int* in_sizes, int n_in,
                              void* d_out, int out_size)
{
    const float* feats_a = (const float*)d_in[0];
    const float* feats_b = (const float*)d_in[1];
    const float* Wih_ca = (const float*)d_in[2];
    const float* Whh_ca = (const float*)d_in[3];
    const float* b_ca   = (const float*)d_in[4];
    const float* Wih_cb = (const float*)d_in[5];
    const float* Whh_cb = (const float*)d_in[6];
    const float* b_cb   = (const float*)d_in[7];
    const float* Wih_na = (const float*)d_in[8];
    const float* Whh_na = (const float*)d_in[9];
    const float* b_na   = (const float*)d_in[10];
    const float* Wih_nb = (const float*)d_in[11];
    const float* Whh_nb = (const float*)d_in[12];
    const float* b_nb   = (const float*)d_in[13];
    const float* attn_a = (const float*)d_in[14];
    const float* attn_b = (const float*)d_in[15];
    const int* idx_a_a = (const int*)d_in[16];
    const int* idx_b_a = (const int*)d_in[17];
    const int* idx_a_b = (const int*)d_in[18];
    const int* idx_b_b = (const int*)d_in[19];
    float* out = (float*)d_out;
    (void)in_sizes; (void)n_in; (void)out_size;

    float *xg, *P0, *P1, *c0, *c1, *n0, *n1, *n2, *n3;
    cudaGetSymbolAddress((void**)&xg, g_xg);
    cudaGetSymbolAddress((void**)&P0, g_P0);
    cudaGetSymbolAddress((void**)&P1, g_P1);
    cudaGetSymbolAddress((void**)&c0, g_c0);
    cudaGetSymbolAddress((void**)&c1, g_c1);
    cudaGetSymbolAddress((void**)&n0, g_n0);
    cudaGetSymbolAddress((void**)&n1, g_n1);
    cudaGetSymbolAddress((void**)&n2, g_n2);
    cudaGetSymbolAddress((void**)&n3, g_n3);

    const size_t GSM = 2u * 128u * 132u * sizeof(float);  // 135168B
    cudaFuncSetAttribute(gemm_gates, cudaFuncAttributeMaxDynamicSharedMemorySize, (int)GSM);

    dim3 ggC(4, (NN * LSEQ + 127) / 128);   // N-slices fastest: A slab L2-hot
    dim3 ggP(4, (NN + 127) / 128);
    const int RB = NN / NB;  // 3750

    // content bi-LSTMs
    gemm_gates<<<ggC, 256, GSM>>>(feats_a, NN * LSEQ, Wih_ca, b_ca, xg);
    recur_kernel<<<RB, 512>>>(xg, nullptr, LSEQ, Whh_ca, c0);
    gemm_gates<<<ggC, 256, GSM>>>(feats_b, NN * LSEQ, Wih_cb, b_cb, xg);
    recur_kernel<<<RB, 512>>>(xg, nullptr, LSEQ, Whh_cb, c1);

    // per-src-node neighbor input gates
    gemm_gates<<<ggP, 256, GSM>>>(c0, NN, Wih_na, b_na, P0);
    gemm_gates<<<ggP, 256, GSM>>>(c1, NN, Wih_nb, b_nb, P1);

    // neighbor bi-LSTMs; P0 consumers adjacent, then P1 (L2 reuse)
    recur_kernel<<<RB, 512>>>(P0, idx_a_a, KFAN, Whh_na, n0);
    recur_kernel<<<RB, 512>>>(P0, idx_a_b, KFAN, Whh_na, n2);
    recur_kernel<<<RB, 512>>>(P1, idx_b_a, KFAN, Whh_nb, n1);
    recur_kernel<<<RB, 512>>>(P1, idx_b_b, KFAN, Whh_nb, n3);

    // attention combine
    combine_kernel<<<(2 * NN * 32 + 255) / 256, 256>>>(
        c0, c1, n0, n1, n2, n3, attn_a, attn_b, out);
}

// round 14
// speedup vs baseline: 1.1577x; 1.0649x over previous
#include <cuda_runtime.h>
#include <cuda_fp16.h>
#include <math.h>
#include <stdint.h>

#define NN    30000
#define LSEQ  5
#define KFAN  16
#define NG    512   // 2 dirs * 4 gates * 64 hidden
#define NB    8     // nodes per recurrence block

// ---------------- scratch (device globals: sanctioned allocation path) ----
__device__ float g_xg[NN * LSEQ * NG];
__device__ float g_P0[NN * NG];
__device__ float g_P1[NN * NG];
__device__ float g_c0[NN * 128];
__device__ float g_c1[NN * 128];
__device__ float g_n0[NN * 128];
__device__ float g_n1[NN * 128];
__device__ float g_n2[NN * 128];
__device__ float g_n3[NN * 128];

// ---------------- fast transcendentals ------------------------------------
__device__ __forceinline__ float ftanh(float x) {
    float y;
    asm("tanh.approx.f32 %0, %1;" : "=f"(y) : "f"(x));
    return y;
}
__device__ __forceinline__ float fsigmoid(float x) {
    return fmaf(ftanh(0.5f * x), 0.5f, 0.5f);
}

// ---------------- GEMM (fp16 m16n8k16 mma) ---------------------------------
// C[m, j] = bias[j] + sum_d A[m,d] * W[j,d]
// A: [M,128] f32 row-major.  W: [512,128] f32 row-major.
// Same 128x128 tile / 8-warp layout as the measured-best tf32 version, but
// fp16 k16 atoms: HALF the k-steps (8), half the fragment LDS, half the MMA
// instructions, half the cvt + smem (68KB -> 2 blocks/SM). fp16 has the same
// 11-bit significand as tf32, fp32 accumulate -> rel_err unchanged.
#define KSTW 68   // smem row stride in uint32 words (half2 pairs); 68%32=4
__global__ __launch_bounds__(256, 2) void gemm_gates(
    const float* __restrict__ A, int M,
    const float* __restrict__ W,
    const float* __restrict__ bias,
    float* __restrict__ C)
{
    extern __shared__ float sm[];
    uint32_t* Au = reinterpret_cast<uint32_t*>(sm);               // [128 m][KSTW]
    uint32_t* Bu = reinterpret_cast<uint32_t*>(sm) + 128 * KSTW;  // [128 n][KSTW]
    __shared__ float sBias[128];
    const int tid = threadIdx.x;
    const int j0 = blockIdx.x * 128;   // N slice (0..3) fastest -> A slab L2-hot
    const int m0 = blockIdx.y * 128;

    if (tid < 128) sBias[tid] = bias[j0 + tid];

    // stage A -> half2 smem [m][k/2], 128 rows x 32 float4 -> 2 words each
    #pragma unroll
    for (int p = 0; p < 16; ++p) {
        int idx = tid + p * 256;       // 0..4095
        int row = idx >> 5;            // 0..127
        int c4  = idx & 31;            // float4 chunk along k
        int gm = m0 + row;
        float4 v = make_float4(0.f, 0.f, 0.f, 0.f);
        if (gm < M) v = reinterpret_cast<const float4*>(A)[(size_t)gm * 32 + c4];
        __half2 h01 = __floats2half2_rn(v.x, v.y);
        __half2 h23 = __floats2half2_rn(v.z, v.w);
        uint2 u = make_uint2(*reinterpret_cast<uint32_t*>(&h01),
                             *reinterpret_cast<uint32_t*>(&h23));
        *reinterpret_cast<uint2*>(&Au[row * KSTW + c4 * 2]) = u;
    }
    // stage W slice -> half2 smem [n][k/2]
    #pragma unroll
    for (int p = 0; p < 16; ++p) {
        int idx = tid + p * 256;
        int row = idx >> 5;
        int c4  = idx & 31;
        float4 v = reinterpret_cast<const float4*>(W)[(size_t)(j0 + row) * 32 + c4];
        __half2 h01 = __floats2half2_rn(v.x, v.y);
        __half2 h23 = __floats2half2_rn(v.z, v.w);
        uint2 u = make_uint2(*reinterpret_cast<uint32_t*>(&h01),
                             *reinterpret_cast<uint32_t*>(&h23));
        *reinterpret_cast<uint2*>(&Bu[row * KSTW + c4 * 2]) = u;
    }
    __syncthreads();

    const int lane = tid & 31;
    const int warp = tid >> 5;     // 0..7
    const int wm = warp & 3;       // 4 m-slices of 32
    const int wn = warp >> 2;      // 2 n-slices of 64
    const int g  = lane >> 2;      // group id (0..7)
    const int tg = lane & 3;       // thread in group (0..3)

    float acc[2][8][4];
    #pragma unroll
    for (int ma = 0; ma < 2; ++ma)
        #pragma unroll
        for (int na = 0; na < 8; ++na)
            #pragma unroll
            for (int e = 0; e < 4; ++e) acc[ma][na][e] = 0.f;

    #pragma unroll
    for (int ks = 0; ks < 8; ++ks) {
        const int k0w = ks * 8;    // word offset (16 f16 = 8 words per step)
        // a fragments: a0={row g, cols 2tg..2tg+1}, a1={row g+8, same},
        //              a2={row g, cols 2tg+8..9},  a3={row g+8, same}
        uint32_t af[2][4];
        #pragma unroll
        for (int ma = 0; ma < 2; ++ma) {
            const uint32_t* ap = Au + (wm * 32 + ma * 16 + g) * KSTW + k0w + tg;
            af[ma][0] = ap[0];
            af[ma][1] = ap[8 * KSTW];
            af[ma][2] = ap[4];
            af[ma][3] = ap[8 * KSTW + 4];
        }
        // b fragments: b0={k 2tg..2tg+1, col g}, b1={k 2tg+8..9, col g}
        uint32_t bf[8][2];
        #pragma unroll
        for (int na = 0; na < 8; ++na) {
            const uint32_t* bp = Bu + (wn * 64 + na * 8 + g) * KSTW + k0w + tg;
            bf[na][0] = bp[0];
            bf[na][1] = bp[4];
        }
        #pragma unroll
        for (int ma = 0; ma < 2; ++ma)
            #pragma unroll
            for (int na = 0; na < 8; ++na)
                asm volatile(
                    "mma.sync.aligned.m16n8k16.row.col.f32.f16.f16.f32 "
                    "{%0,%1,%2,%3}, {%4,%5,%6,%7}, {%8,%9}, {%0,%1,%2,%3};"
                    : "+f"(acc[ma][na][0]), "+f"(acc[ma][na][1]),
                      "+f"(acc[ma][na][2]), "+f"(acc[ma][na][3])
                    : "r"(af[ma][0]), "r"(af[ma][1]), "r"(af[ma][2]), "r"(af[ma][3]),
                      "r"(bf[na][0]), "r"(bf[na][1]));
    }

    // epilogue: bias + store (c0,c1 = row g pair; c2,c3 = row g+8)
    #pragma unroll
    for (int ma = 0; ma < 2; ++ma) {
        #pragma unroll
        for (int half = 0; half < 2; ++half) {
            int gm = m0 + wm * 32 + ma * 16 + g + half * 8;
            if (gm < M) {
                float* Crow = C + (size_t)gm * NG + j0;
                #pragma unroll
                for (int na = 0; na < 8; ++na) {
                    int n = wn * 64 + na * 8 + tg * 2;
                    float2 o;
                    o.x = acc[ma][na][half * 2 + 0] + sBias[n];
                    o.y = acc[ma][na][half * 2 + 1] + sBias[n + 1];
                    *reinterpret_cast<float2*>(Crow + n) = o;
                }
            }
        }
    }
}

// ---------------- bi-LSTM recurrence + mean (measured-good v2) -------------
__global__ __launch_bounds__(512, 1) void recur_kernel(
    const float* __restrict__ xg,
    const int* __restrict__ idx,
    int T,
    const float* __restrict__ Whh,
    float* __restrict__ out)
{
    __shared__ float h_s[NB][128];
    __shared__ float g_s[NB][NG];
    __shared__ int   sIdx[NB * 17];
    const int tid = threadIdx.x;
    const int dir = tid >> 8;
    const int node0 = blockIdx.x * NB;

    if (tid < NB * T) {
        int i = tid / T, t = tid % T;
        int seq = (node0 + i) * T + t;
        sIdx[i * 17 + t] = idx ? idx[seq] : seq;
    }

    float whh[64];
    {
        const float4* wp = reinterpret_cast<const float4*>(Whh + (size_t)tid * 64);
        #pragma unroll
        for (int e4 = 0; e4 < 16; ++e4) {
            float4 v = wp[e4];
            whh[e4 * 4 + 0] = v.x; whh[e4 * 4 + 1] = v.y;
            whh[e4 * 4 + 2] = v.z; whh[e4 * 4 + 3] = v.w;
        }
    }

    float cst[2]  = {0.f, 0.f};
    float hsum[2] = {0.f, 0.f};
    #pragma unroll
    for (int q = 0; q < 2; ++q) {
        int u = tid + q * 512;
        h_s[u >> 7][u & 127] = 0.f;
    }
    __syncthreads();

    float cur[NB], nxt[NB];
    #pragma unroll
    for (int i = 0; i < NB; ++i) nxt[i] = 0.f;
    {
        const int trow = dir ? (T - 1) : 0;
        #pragma unroll
        for (int i = 0; i < NB; ++i)
            cur[i] = xg[(size_t)sIdx[i * 17 + trow] * NG + tid];
    }

    for (int t = 0; t < T; ++t) {
        if (t + 1 < T) {
            const int trow = dir ? (T - 2 - t) : (t + 1);
            #pragma unroll
            for (int i = 0; i < NB; ++i)
                nxt[i] = xg[(size_t)sIdx[i * 17 + trow] * NG + tid];
        }

        #pragma unroll
        for (int i = 0; i < NB; ++i) {
            const float4* h4 = reinterpret_cast<const float4*>(&h_s[i][dir * 64]);
            float a0 = cur[i], a1 = 0.f;
            #pragma unroll
            for (int e4 = 0; e4 < 16; e4 += 2) {
                float4 ha = h4[e4];
                float4 hb = h4[e4 + 1];
                a0 += whh[e4 * 4 + 0] * ha.x;
                a0 += whh[e4 * 4 + 1] * ha.y;
                a0 += whh[e4 * 4 + 2] * ha.z;
                a0 += whh[e4 * 4 + 3] * ha.w;
                a1 += whh[e4 * 4 + 4] * hb.x;
                a1 += whh[e4 * 4 + 5] * hb.y;
                a1 += whh[e4 * 4 + 6] * hb.z;
                a1 += whh[e4 * 4 + 7] * hb.w;
            }
            g_s[i][tid] = a0 + a1;
        }
        __syncthreads();

        #pragma unroll
        for (int q = 0; q < 2; ++q) {
            int u = tid + q * 512;
            int i = u >> 7, r = u & 127;
            int dd = r >> 6, e = r & 63;
            const float* gg = &g_s[i][dd * 256];
            float si = fsigmoid(gg[e]);
            float sf = fsigmoid(gg[64 + e]);
            float so = fsigmoid(gg[192 + e]);
            float gt = ftanh(gg[128 + e]);
            float c = sf * cst[q] + si * gt;
            float h = so * ftanh(c);
            cst[q] = c;
            h_s[i][r] = h;
            hsum[q] += h;
        }
        __syncthreads();

        #pragma unroll
        for (int i = 0; i < NB; ++i) cur[i] = nxt[i];
    }

    const float invT = 1.f / (float)T;
    #pragma unroll
    for (int q = 0; q < 2; ++q) {
        int u = tid + q * 512;
        int i = u >> 7, r = u & 127;
        out[(size_t)(node0 + i) * 128 + r] = hsum[q] * invT;
    }
}

// ---------------- attention combine ---------------------------------------
__global__ void combine_kernel(
    const float* __restrict__ cA, const float* __restrict__ cB,
    const float* __restrict__ nAA, const float* __restrict__ nBA,
    const float* __restrict__ nAB, const float* __restrict__ nBB,
    const float* __restrict__ attnA, const float* __restrict__ attnB,
    float* __restrict__ out)
{
    int gw   = (blockIdx.x * blockDim.x + threadIdx.x) >> 5;
    int lane = threadIdx.x & 31;
    if (gw >= 2 * NN) return;
    int tp = gw >= NN;
    int node = gw - tp * NN;

    const float* c  = (tp ? cB  : cA)  + (size_t)node * 128;
    const float* n1 = (tp ? nAB : nAA) + (size_t)node * 128;
    const float* n2 = (tp ? nBB : nBA) + (size_t)node * 128;
    const float* at = tp ? attnB : attnA;

    float4 c4  = reinterpret_cast<const float4*>(c)[lane];
    float4 n14 = reinterpret_cast<const float4*>(n1)[lane];
    float4 n24 = reinterpret_cast<const float4*>(n2)[lane];
    float4 a1  = reinterpret_cast<const float4*>(at)[lane];
    float4 a2  = reinterpret_cast<const float4*>(at + 128)[lane];

    float d0 = a1.x * c4.x + a1.y * c4.y + a1.z * c4.z + a1.w * c4.w;
    float dc = a2.x * c4.x + a2.y * c4.y + a2.z * c4.z + a2.w * c4.w;
    float d1 = a2.x * n14.x + a2.y * n14.y + a2.z * n14.z + a2.w * n14.w;
    float d2 = a2.x * n24.x + a2.y * n24.y + a2.z * n24.z + a2.w * n24.w;
    #pragma unroll
    for (int o = 16; o > 0; o >>= 1) {
        d0 += __shfl_xor_sync(0xffffffffu, d0, o);
        dc += __shfl_xor_sync(0xffffffffu, dc, o);
        d1 += __shfl_xor_sync(0xffffffffu, d1, o);
        d2 += __shfl_xor_sync(0xffffffffu, d2, o);
    }
    float s0 = d0 + dc; s0 = s0 > 0.f ? s0 : 0.01f * s0;
    float s1 = d0 + d1; s1 = s1 > 0.f ? s1 : 0.01f * s1;
    float s2 = d0 + d2; s2 = s2 > 0.f ? s2 : 0.01f * s2;
    float mx = fmaxf(s0, fmaxf(s1, s2));
    float e0 = expf(s0 - mx), e1 = expf(s1 - mx), e2 = expf(s2 - mx);
    float inv = 1.f / (e0 + e1 + e2);
    e0 *= inv; e1 *= inv; e2 *= inv;

    float4 o4;
    o4.x = e0 * c4.x + e1 * n14.x + e2 * n24.x;
    o4.y = e0 * c4.y + e1 * n14.y + e2 * n24.y;
    o4.z = e0 * c4.z + e1 * n14.z + e2 * n24.z;
    o4.w = e0 * c4.w + e1 * n14.w + e2 * n24.w;
    reinterpret_cast<float4*>(out + (size_t)tp * NN * 128 + (size_t)node * 128)[lane] = o4;
}

// ---------------- launch ---------------------------------------------------
extern "C" void kernel_launch(void* const* d_in, const int* in_sizes, int n_in,
                              void* d_out, int out_size)
{
    const float* feats_a = (const float*)d_in[0];
    const float* feats_b = (const float*)d_in[1];
    const float* Wih_ca = (const float*)d_in[2];
    const float* Whh_ca = (const float*)d_in[3];
    const float* b_ca   = (const float*)d_in[4];
    const float* Wih_cb = (const float*)d_in[5];
    const float* Whh_cb = (const float*)d_in[6];
    const float* b_cb   = (const float*)d_in[7];
    const float* Wih_na = (const float*)d_in[8];
    const float* Whh_na = (const float*)d_in[9];
    const float* b_na   = (const float*)d_in[10];
    const float* Wih_nb = (const float*)d_in[11];
    const float* Whh_nb = (const float*)d_in[12];
    const float* b_nb   = (const float*)d_in[13];
    const float* attn_a = (const float*)d_in[14];
    const float* attn_b = (const float*)d_in[15];
    const int* idx_a_a = (const int*)d_in[16];
    const int* idx_b_a = (const int*)d_in[17];
    const int* idx_a_b = (const int*)d_in[18];
    const int* idx_b_b = (const int*)d_in[19];
    float* out = (float*)d_out;
    (void)in_sizes; (void)n_in; (void)out_size;

    float *xg, *P0, *P1, *c0, *c1, *n0, *n1, *n2, *n3;
    cudaGetSymbolAddress((void**)&xg, g_xg);
    cudaGetSymbolAddress((void**)&P0, g_P0);
    cudaGetSymbolAddress((void**)&P1, g_P1);
    cudaGetSymbolAddress((void**)&c0, g_c0);
    cudaGetSymbolAddress((void**)&c1, g_c1);
    cudaGetSymbolAddress((void**)&n0, g_n0);
    cudaGetSymbolAddress((void**)&n1, g_n1);
    cudaGetSymbolAddress((void**)&n2, g_n2);
    cudaGetSymbolAddress((void**)&n3, g_n3);

    const size_t GSM = 2u * 128u * KSTW * sizeof(uint32_t);  // 69632B
    cudaFuncSetAttribute(gemm_gates, cudaFuncAttributeMaxDynamicSharedMemorySize, (int)GSM);

    dim3 ggC(4, (NN * LSEQ + 127) / 128);   // N-slices fastest: A slab L2-hot
    dim3 ggP(4, (NN + 127) / 128);
    const int RB = NN / NB;  // 3750

    // content bi-LSTMs
    gemm_gates<<<ggC, 256, GSM>>>(feats_a, NN * LSEQ, Wih_ca, b_ca, xg);
    recur_kernel<<<RB, 512>>>(xg, nullptr, LSEQ, Whh_ca, c0);
    gemm_gates<<<ggC, 256, GSM>>>(feats_b, NN * LSEQ, Wih_cb, b_cb, xg);
    recur_kernel<<<RB, 512>>>(xg, nullptr, LSEQ, Whh_cb, c1);

    // per-src-node neighbor input gates
    gemm_gates<<<ggP, 256, GSM>>>(c0, NN, Wih_na, b_na, P0);
    gemm_gates<<<ggP, 256, GSM>>>(c1, NN, Wih_nb, b_nb, P1);

    // neighbor bi-LSTMs; P0 consumers adjacent, then P1 (L2 reuse)
    recur_kernel<<<RB, 512>>>(P0, idx_a_a, KFAN, Whh_na, n0);
    recur_kernel<<<RB, 512>>>(P0, idx_a_b, KFAN, Whh_na, n2);
    recur_kernel<<<RB, 512>>>(P1, idx_b_a, KFAN, Whh_nb, n1);
    recur_kernel<<<RB, 512>>>(P1, idx_b_b, KFAN, Whh_nb, n3);

    // attention combine
    combine_kernel<<<(2 * NN * 32 + 255) / 256, 256>>>(
        c0, c1, n0, n1, n2, n3, attn_a, attn_b, out);
}